// round 13
// baseline (speedup 1.0000x reference)
#include <cuda_runtime.h>
#include <cstdint>
#include <math_constants.h>

// Farthest point sampling, NPOINT=2.
// Input: xyz [1, B=32, 3, N] float32 (planar per batch: x-plane, y-plane, z-plane).
// Output (float32, [B,2]): idx0 = argmax over y-plane; idx1 = argmax of squared
// distance to point idx0 (first-index tiebreak, matching jnp.argmax).
//
// 2 launches:
//   pass1: y argmax partials, 256-bit loads, x2 unroll, forward sweep; resets ticket.
//   pass2: distance argmax partials, single accumulator, REVERSE sweep, 8-wide
//          chunks with liveness staging (x: one 256-bit .cs load; z,y: staged
//          16B halves) -> no spills at the 32-reg cap; last block folds the
//          final reduction + output write (threadfence-reduction).

#define FPS_B 32
#define BPB   37            // 37*32 = 1184 blocks = one full wave (148 SM x 8 CTA)

__device__ unsigned long long g_part1[FPS_B * BPB];
__device__ unsigned long long g_part2[FPS_B * BPB];
__device__ unsigned int       g_ticket;

struct F8 { float f[8]; };

// 32-byte read-only load (LDG.E.256), default cache policy.
static __device__ __forceinline__ F8 ldg8(const float* p) {
    unsigned long long a, b, c, d;
    asm("ld.global.nc.v4.b64 {%0,%1,%2,%3}, [%4];"
        : "=l"(a), "=l"(b), "=l"(c), "=l"(d) : "l"(p));
    F8 r;
    r.f[0] = __uint_as_float((unsigned)a);  r.f[1] = __uint_as_float((unsigned)(a >> 32));
    r.f[2] = __uint_as_float((unsigned)b);  r.f[3] = __uint_as_float((unsigned)(b >> 32));
    r.f[4] = __uint_as_float((unsigned)c);  r.f[5] = __uint_as_float((unsigned)(c >> 32));
    r.f[6] = __uint_as_float((unsigned)d);  r.f[7] = __uint_as_float((unsigned)(d >> 32));
    return r;
}

// 32-byte streaming load (evict-first), for the x-plane in pass 2.
static __device__ __forceinline__ F8 ldg8_cs(const float* p) {
    unsigned long long a, b, c, d;
    asm("ld.global.cs.v4.b64 {%0,%1,%2,%3}, [%4];"
        : "=l"(a), "=l"(b), "=l"(c), "=l"(d) : "l"(p));
    F8 r;
    r.f[0] = __uint_as_float((unsigned)a);  r.f[1] = __uint_as_float((unsigned)(a >> 32));
    r.f[2] = __uint_as_float((unsigned)b);  r.f[3] = __uint_as_float((unsigned)(b >> 32));
    r.f[4] = __uint_as_float((unsigned)c);  r.f[5] = __uint_as_float((unsigned)(c >> 32));
    r.f[6] = __uint_as_float((unsigned)d);  r.f[7] = __uint_as_float((unsigned)(d >> 32));
    return r;
}

// key = (ordered_float(val) << 32) | ~index : max-key == (max val, min index on tie)
static __device__ __forceinline__ unsigned long long make_key(float v, unsigned idx) {
    unsigned u = __float_as_uint(v);
    u = (u & 0x80000000u) ? ~u : (u | 0x80000000u);
    return ((unsigned long long)u << 32) | (unsigned)(~idx);
}

static __device__ __forceinline__ unsigned long long umax64(unsigned long long a,
                                                            unsigned long long b) {
    return a > b ? a : b;
}

// full block max (result valid in thread 0 of warp 0)
static __device__ __forceinline__ unsigned long long block_reduce_max(unsigned long long v) {
    __shared__ unsigned long long s[8];
    int lane = threadIdx.x & 31;
    int wid  = threadIdx.x >> 5;
    #pragma unroll
    for (int o = 16; o; o >>= 1)
        v = umax64(v, __shfl_down_sync(0xffffffffu, v, o));
    if (lane == 0) s[wid] = v;
    __syncthreads();
    if (wid == 0) {
        v = (lane < (int)(blockDim.x >> 5)) ? s[lane] : 0ull;
        #pragma unroll
        for (int o = 16; o; o >>= 1)
            v = umax64(v, __shfl_down_sync(0xffffffffu, v, o));
    }
    return v;
}

// forward order: keeps FIRST index on tie via >
#define UPD_GT(bv, bi, v, i) do { if ((v) > (bv)) { (bv) = (v); (bi) = (i); } } while (0)
// reverse order: later-seen index is smaller -> prefer on tie via >=
#define UPD_GE(bv, bi, v, i) do { if ((v) >= (bv)) { (bv) = (v); (bi) = (i); } } while (0)

// Pass 1: per-batch argmax over the y-plane (channel 1). Forward sweep so the
// y tail is L2-resident when pass 2's reverse sweep starts. 32B loads, x2 unroll.
__global__ void __launch_bounds__(256, 8)
fps_pass1(const float* __restrict__ xyz, int N) {
    if (blockIdx.x == 0 && blockIdx.y == 0 && threadIdx.x == 0) g_ticket = 0;

    const int b = blockIdx.y;
    const float* yp = xyz + (size_t)b * 3 * N + (size_t)N;
    const int N8 = N >> 3;
    const int S = gridDim.x * blockDim.x;

    float    bv0 = -CUDART_INF_F, bv1 = -CUDART_INF_F;
    unsigned bi0 = 0u, bi1 = 0u;

    int i = blockIdx.x * blockDim.x + threadIdx.x;
    for (; i + S < N8; i += 2 * S) {
        F8 a = ldg8(yp + ((size_t)i << 3));
        F8 c = ldg8(yp + ((size_t)(i + S) << 3));
        unsigned ba = (unsigned)(i << 3);
        unsigned bc = (unsigned)((i + S) << 3);
        #pragma unroll
        for (int e = 0; e < 8; e++) UPD_GT(bv0, bi0, a.f[e], ba + e);
        #pragma unroll
        for (int e = 0; e < 8; e++) UPD_GT(bv1, bi1, c.f[e], bc + e);
    }
    for (; i < N8; i += S) {
        F8 a = ldg8(yp + ((size_t)i << 3));
        unsigned ba = (unsigned)(i << 3);
        #pragma unroll
        for (int e = 0; e < 8; e++) UPD_GT(bv0, bi0, a.f[e], ba + e);
    }
    unsigned long long best = umax64(make_key(bv0, bi0), make_key(bv1, bi1));

    if (blockIdx.x == 0) {   // scalar tail (N % 8)
        float bvt = -CUDART_INF_F; unsigned bit_ = 0u;
        for (int t = (N8 << 3) + threadIdx.x; t < N; t += blockDim.x)
            UPD_GT(bvt, bit_, yp[t], (unsigned)t);
        best = umax64(best, make_key(bvt, bit_));
    }

    best = block_reduce_max(best);
    if (threadIdx.x == 0) g_part1[b * BPB + blockIdx.x] = best;
}

// Pass 2: per-batch argmax of min(1e10, ||p - c0||^2), reverse sweep, 8-wide
// chunks. x: one 256-bit streaming load; z: staged 16B streaming halves;
// y: staged 16B default-cached halves (hot from pass 1). Elements processed
// 7..0 within a chunk, chunks in descending order -> '>=' tiebreak exact.
// Last block performs the global reduction and writes the output.
__global__ void __launch_bounds__(256, 8)
fps_pass2(const float* __restrict__ xyz, int N, float* __restrict__ out) {
    const int b = blockIdx.y;

    // reduce pass-1 partials for this batch -> centroid index
    __shared__ unsigned idx0_sh;
    {
        unsigned long long v = (threadIdx.x < BPB) ? g_part1[b * BPB + threadIdx.x] : 0ull;
        v = block_reduce_max(v);
        if (threadIdx.x == 0) idx0_sh = ~(unsigned)v;
        __syncthreads();
    }
    const unsigned idx0 = idx0_sh;

    const float* xp = xyz + (size_t)b * 3 * N;
    const float* yp = xp + (size_t)N;
    const float* zp = xp + (size_t)2 * N;
    const float cx = __ldg(xp + idx0);
    const float cy = __ldg(yp + idx0);
    const float cz = __ldg(zp + idx0);

    const int N8 = N >> 3;
    const int S = gridDim.x * blockDim.x;

    float    bv = -CUDART_INF_F;
    unsigned bi = 0u;

    // scalar tail first (highest indices), forward '>' keeps first; the main
    // loop below visits strictly smaller indices with '>=', overriding ties.
    if (blockIdx.x == 0) {
        for (int t = (N8 << 3) + threadIdx.x; t < N; t += blockDim.x) {
            float dx = xp[t] - cx, dy = yp[t] - cy, dz = zp[t] - cz;
            float d = fminf(dx * dx + dy * dy + dz * dz, 1e10f);
            UPD_GT(bv, bi, d, (unsigned)t);
        }
    }

    for (int j = blockIdx.x * blockDim.x + threadIdx.x; j < N8; j += S) {
        int i = N8 - 1 - j;                    // reverse: hot y tail consumed first
        size_t e0 = (size_t)i << 3;
        unsigned base = (unsigned)e0;

        F8 vx = ldg8_cs(xp + e0);              // 256-bit streaming
        // stage HIGH halves first (processed first: descending order)
        float4 vz1 = __ldcs((const float4*)(zp + e0) + 1);   // z elements 4..7
        float4 vy1 = *((const float4*)(yp + e0) + 1);        // y elements 4..7 (cached)
        {
            float dx = vx.f[7] - cx, dy = vy1.w - cy, dz = vz1.w - cz;
            float d = fminf(dx * dx + dy * dy + dz * dz, 1e10f);
            UPD_GE(bv, bi, d, base + 7);
        }
        {
            float dx = vx.f[6] - cx, dy = vy1.z - cy, dz = vz1.z - cz;
            float d = fminf(dx * dx + dy * dy + dz * dz, 1e10f);
            UPD_GE(bv, bi, d, base + 6);
        }
        {
            float dx = vx.f[5] - cx, dy = vy1.y - cy, dz = vz1.y - cz;
            float d = fminf(dx * dx + dy * dy + dz * dz, 1e10f);
            UPD_GE(bv, bi, d, base + 5);
        }
        {
            float dx = vx.f[4] - cx, dy = vy1.x - cy, dz = vz1.x - cz;
            float d = fminf(dx * dx + dy * dy + dz * dz, 1e10f);
            UPD_GE(bv, bi, d, base + 4);
        }
        // LOW halves
        float4 vz0 = __ldcs((const float4*)(zp + e0));       // z elements 0..3
        float4 vy0 = *((const float4*)(yp + e0));            // y elements 0..3 (cached)
        {
            float dx = vx.f[3] - cx, dy = vy0.w - cy, dz = vz0.w - cz;
            float d = fminf(dx * dx + dy * dy + dz * dz, 1e10f);
            UPD_GE(bv, bi, d, base + 3);
        }
        {
            float dx = vx.f[2] - cx, dy = vy0.z - cy, dz = vz0.z - cz;
            float d = fminf(dx * dx + dy * dy + dz * dz, 1e10f);
            UPD_GE(bv, bi, d, base + 2);
        }
        {
            float dx = vx.f[1] - cx, dy = vy0.y - cy, dz = vz0.y - cz;
            float d = fminf(dx * dx + dy * dy + dz * dz, 1e10f);
            UPD_GE(bv, bi, d, base + 1);
        }
        {
            float dx = vx.f[0] - cx, dy = vy0.x - cy, dz = vz0.x - cz;
            float d = fminf(dx * dx + dy * dy + dz * dz, 1e10f);
            UPD_GE(bv, bi, d, base + 0);
        }
    }

    unsigned long long best = block_reduce_max(make_key(bv, bi));
    if (threadIdx.x == 0) g_part2[b * BPB + blockIdx.x] = best;

    // ---- folded finalize: last block reduces all partials, writes output ----
    __shared__ bool s_last;
    __threadfence();
    if (threadIdx.x == 0) {
        unsigned t = atomicAdd(&g_ticket, 1u);
        s_last = (t == gridDim.x * gridDim.y - 1);
    }
    __syncthreads();
    if (s_last) {
        int wid  = threadIdx.x >> 5;
        int lane = threadIdx.x & 31;
        for (int bb = wid; bb < FPS_B; bb += (int)(blockDim.x >> 5)) {
            unsigned long long v1 = 0ull, v2 = 0ull;
            for (int k = lane; k < BPB; k += 32) {
                v1 = umax64(v1, g_part1[bb * BPB + k]);
                v2 = umax64(v2, g_part2[bb * BPB + k]);
            }
            #pragma unroll
            for (int o = 16; o; o >>= 1) {
                v1 = umax64(v1, __shfl_down_sync(0xffffffffu, v1, o));
                v2 = umax64(v2, __shfl_down_sync(0xffffffffu, v2, o));
            }
            if (lane == 0) {
                out[2 * bb + 0] = (float)(~(unsigned)v1);   // exact: idx <= 2^24
                out[2 * bb + 1] = (float)(~(unsigned)v2);
            }
        }
    }
}

extern "C" void kernel_launch(void* const* d_in, const int* in_sizes, int n_in,
                              void* d_out, int out_size) {
    const float* xyz = (const float*)d_in[0];
    const int N = in_sizes[0] / (FPS_B * 3);   // [1, 32, 3, N]
    float* out = (float*)d_out;

    const int THREADS = 256;
    fps_pass1<<<dim3(BPB, FPS_B), THREADS>>>(xyz, N);
    fps_pass2<<<dim3(BPB, FPS_B), THREADS>>>(xyz, N, out);
}

// round 14
// speedup vs baseline: 1.1805x; 1.1805x over previous
#include <cuda_runtime.h>
#include <cstdint>
#include <math_constants.h>

// Farthest point sampling, NPOINT=2.
// Input: xyz [1, B=32, 3, N] float32 (planar per batch: x-plane, y-plane, z-plane).
// Output (float32, [B,2]): idx0 = argmax over y-plane; idx1 = argmax of squared
// distance to point idx0 (first-index tiebreak, matching jnp.argmax).
//
// 2 launches (best measured configuration, R11 = 66.3 us):
//   pass1: y argmax partials, 256-bit loads (ld.global.nc.v4.b64), x2 unroll,
//          forward sweep; resets ticket.
//   pass2: distance argmax partials, single accumulator (regs<=32 -> one wave),
//          REVERSE sweep for L2 reuse of y, x/z evict-first; last block folds
//          the final reduction + output write (threadfence-reduction).

#define FPS_B 32
#define BPB   37            // 37*32 = 1184 blocks = one full wave (148 SM x 8 CTA)

__device__ unsigned long long g_part1[FPS_B * BPB];
__device__ unsigned long long g_part2[FPS_B * BPB];
__device__ unsigned int       g_ticket;

struct F8 { float f[8]; };

// 32-byte read-only load (LDG.E.256). Hi-word extracts are free (register pair).
static __device__ __forceinline__ F8 ldg8(const float* p) {
    unsigned long long a, b, c, d;
    asm("ld.global.nc.v4.b64 {%0,%1,%2,%3}, [%4];"
        : "=l"(a), "=l"(b), "=l"(c), "=l"(d) : "l"(p));
    F8 r;
    r.f[0] = __uint_as_float((unsigned)a);  r.f[1] = __uint_as_float((unsigned)(a >> 32));
    r.f[2] = __uint_as_float((unsigned)b);  r.f[3] = __uint_as_float((unsigned)(b >> 32));
    r.f[4] = __uint_as_float((unsigned)c);  r.f[5] = __uint_as_float((unsigned)(c >> 32));
    r.f[6] = __uint_as_float((unsigned)d);  r.f[7] = __uint_as_float((unsigned)(d >> 32));
    return r;
}

// key = (ordered_float(val) << 32) | ~index : max-key == (max val, min index on tie)
static __device__ __forceinline__ unsigned long long make_key(float v, unsigned idx) {
    unsigned u = __float_as_uint(v);
    u = (u & 0x80000000u) ? ~u : (u | 0x80000000u);
    return ((unsigned long long)u << 32) | (unsigned)(~idx);
}

static __device__ __forceinline__ unsigned long long umax64(unsigned long long a,
                                                            unsigned long long b) {
    return a > b ? a : b;
}

// full block max (result valid in thread 0 of warp 0)
static __device__ __forceinline__ unsigned long long block_reduce_max(unsigned long long v) {
    __shared__ unsigned long long s[8];
    int lane = threadIdx.x & 31;
    int wid  = threadIdx.x >> 5;
    #pragma unroll
    for (int o = 16; o; o >>= 1)
        v = umax64(v, __shfl_down_sync(0xffffffffu, v, o));
    if (lane == 0) s[wid] = v;
    __syncthreads();
    if (wid == 0) {
        v = (lane < (int)(blockDim.x >> 5)) ? s[lane] : 0ull;
        #pragma unroll
        for (int o = 16; o; o >>= 1)
            v = umax64(v, __shfl_down_sync(0xffffffffu, v, o));
    }
    return v;
}

// forward order: keeps FIRST index on tie via >
#define UPD_GT(bv, bi, v, i) do { if ((v) > (bv)) { (bv) = (v); (bi) = (i); } } while (0)
// reverse order: later-seen index is smaller -> prefer on tie via >=
#define UPD_GE(bv, bi, v, i) do { if ((v) >= (bv)) { (bv) = (v); (bi) = (i); } } while (0)

// Pass 1: per-batch argmax over the y-plane (channel 1). Forward sweep so the
// y tail is L2-resident when pass 2's reverse sweep starts. 32B loads, x2 unroll.
__global__ void __launch_bounds__(256, 8)
fps_pass1(const float* __restrict__ xyz, int N) {
    if (blockIdx.x == 0 && blockIdx.y == 0 && threadIdx.x == 0) g_ticket = 0;

    const int b = blockIdx.y;
    const float* yp = xyz + (size_t)b * 3 * N + (size_t)N;
    const int N8 = N >> 3;
    const int S = gridDim.x * blockDim.x;

    float    bv0 = -CUDART_INF_F, bv1 = -CUDART_INF_F;
    unsigned bi0 = 0u, bi1 = 0u;

    int i = blockIdx.x * blockDim.x + threadIdx.x;
    for (; i + S < N8; i += 2 * S) {
        F8 a = ldg8(yp + ((size_t)i << 3));
        F8 c = ldg8(yp + ((size_t)(i + S) << 3));
        unsigned ba = (unsigned)(i << 3);
        unsigned bc = (unsigned)((i + S) << 3);
        #pragma unroll
        for (int e = 0; e < 8; e++) UPD_GT(bv0, bi0, a.f[e], ba + e);
        #pragma unroll
        for (int e = 0; e < 8; e++) UPD_GT(bv1, bi1, c.f[e], bc + e);
    }
    for (; i < N8; i += S) {
        F8 a = ldg8(yp + ((size_t)i << 3));
        unsigned ba = (unsigned)(i << 3);
        #pragma unroll
        for (int e = 0; e < 8; e++) UPD_GT(bv0, bi0, a.f[e], ba + e);
    }
    unsigned long long best = umax64(make_key(bv0, bi0), make_key(bv1, bi1));

    if (blockIdx.x == 0) {   // scalar tail (N % 8)
        float bvt = -CUDART_INF_F; unsigned bit_ = 0u;
        for (int t = (N8 << 3) + threadIdx.x; t < N; t += blockDim.x)
            UPD_GT(bvt, bit_, yp[t], (unsigned)t);
        best = umax64(best, make_key(bvt, bit_));
    }

    best = block_reduce_max(best);
    if (threadIdx.x == 0) g_part1[b * BPB + blockIdx.x] = best;
}

// Pass 2: per-batch argmax of min(1e10, ||p - c0||^2), reverse sweep (single
// accumulator -> regs<=32 -> one full wave). x,z evict-first; y default-cached
// (hot from pass 1). Last block performs the global reduction + output write.
__global__ void __launch_bounds__(256, 8)
fps_pass2(const float* __restrict__ xyz, int N, float* __restrict__ out) {
    const int b = blockIdx.y;

    // reduce pass-1 partials for this batch -> centroid index
    __shared__ unsigned idx0_sh;
    {
        unsigned long long v = (threadIdx.x < BPB) ? g_part1[b * BPB + threadIdx.x] : 0ull;
        v = block_reduce_max(v);
        if (threadIdx.x == 0) idx0_sh = ~(unsigned)v;
        __syncthreads();
    }
    const unsigned idx0 = idx0_sh;

    const float* xp = xyz + (size_t)b * 3 * N;
    const float* yp = xp + (size_t)N;
    const float* zp = xp + (size_t)2 * N;
    const float cx = __ldg(xp + idx0);
    const float cy = __ldg(yp + idx0);
    const float cz = __ldg(zp + idx0);

    const int N4 = N >> 2;
    const float4* x4 = (const float4*)xp;
    const float4* y4 = (const float4*)yp;
    const float4* z4 = (const float4*)zp;
    const int stride = gridDim.x * blockDim.x;

    float    bv = -CUDART_INF_F;
    unsigned bi = 0u;

    // scalar tail first (highest indices), forward order -> '>' keeps first;
    // main loop's GE (strictly smaller indices) correctly overrides ties after.
    if (blockIdx.x == 0) {
        for (int t = (N4 << 2) + threadIdx.x; t < N; t += blockDim.x) {
            float dx = xp[t] - cx, dy = yp[t] - cy, dz = zp[t] - cz;
            float d = fminf(dx * dx + dy * dy + dz * dz, 1e10f);
            UPD_GT(bv, bi, d, (unsigned)t);
        }
    }

    for (int j = blockIdx.x * blockDim.x + threadIdx.x; j < N4; j += stride) {
        int i = N4 - 1 - j;                    // reverse: hot y tail consumed first
        float4 vx = __ldcs(x4 + i);            // streaming, evict-first
        float4 vy = y4[i];                     // hot from pass 1 -> keep cached
        float4 vz = __ldcs(z4 + i);
        unsigned base = (unsigned)(i << 2);
        {
            float dx = vx.x - cx, dy = vy.x - cy, dz = vz.x - cz;
            float d = fminf(dx * dx + dy * dy + dz * dz, 1e10f);
            UPD_GE(bv, bi, d, base + 0);
        }
        {
            float dx = vx.y - cx, dy = vy.y - cy, dz = vz.y - cz;
            float d = fminf(dx * dx + dy * dy + dz * dz, 1e10f);
            UPD_GE(bv, bi, d, base + 1);
        }
        {
            float dx = vx.z - cx, dy = vy.z - cy, dz = vz.z - cz;
            float d = fminf(dx * dx + dy * dy + dz * dz, 1e10f);
            UPD_GE(bv, bi, d, base + 2);
        }
        {
            float dx = vx.w - cx, dy = vy.w - cy, dz = vz.w - cz;
            float d = fminf(dx * dx + dy * dy + dz * dz, 1e10f);
            UPD_GE(bv, bi, d, base + 3);
        }
    }

    unsigned long long best = block_reduce_max(make_key(bv, bi));
    if (threadIdx.x == 0) g_part2[b * BPB + blockIdx.x] = best;

    // ---- folded finalize: last block reduces all partials, writes output ----
    __shared__ bool s_last;
    __threadfence();
    if (threadIdx.x == 0) {
        unsigned t = atomicAdd(&g_ticket, 1u);
        s_last = (t == gridDim.x * gridDim.y - 1);
    }
    __syncthreads();
    if (s_last) {
        int wid  = threadIdx.x >> 5;
        int lane = threadIdx.x & 31;
        for (int bb = wid; bb < FPS_B; bb += (int)(blockDim.x >> 5)) {
            unsigned long long v1 = 0ull, v2 = 0ull;
            for (int k = lane; k < BPB; k += 32) {
                v1 = umax64(v1, g_part1[bb * BPB + k]);
                v2 = umax64(v2, g_part2[bb * BPB + k]);
            }
            #pragma unroll
            for (int o = 16; o; o >>= 1) {
                v1 = umax64(v1, __shfl_down_sync(0xffffffffu, v1, o));
                v2 = umax64(v2, __shfl_down_sync(0xffffffffu, v2, o));
            }
            if (lane == 0) {
                out[2 * bb + 0] = (float)(~(unsigned)v1);   // exact: idx <= 2^24
                out[2 * bb + 1] = (float)(~(unsigned)v2);
            }
        }
    }
}

extern "C" void kernel_launch(void* const* d_in, const int* in_sizes, int n_in,
                              void* d_out, int out_size) {
    const float* xyz = (const float*)d_in[0];
    const int N = in_sizes[0] / (FPS_B * 3);   // [1, 32, 3, N]
    float* out = (float*)d_out;

    const int THREADS = 256;
    fps_pass1<<<dim3(BPB, FPS_B), THREADS>>>(xyz, N);
    fps_pass2<<<dim3(BPB, FPS_B), THREADS>>>(xyz, N, out);
}

// round 15
// speedup vs baseline: 1.2129x; 1.0275x over previous
#include <cuda_runtime.h>
#include <cstdint>
#include <math_constants.h>

// Farthest point sampling, NPOINT=2.  [FINAL — converged configuration]
// Input: xyz [1, B=32, 3, N] float32 (planar per batch: x-plane, y-plane, z-plane).
// Output (float32, [B,2]): idx0 = argmax over y-plane; idx1 = argmax of squared
// distance to point idx0 (first-index tiebreak, matching jnp.argmax).
//
// 2 launches:
//   pass1: y argmax partials, 256-bit loads (ld.global.nc.v4.b64), x2 unroll,
//          forward sweep; resets ticket.
//   pass2: distance argmax partials, single accumulator (regs<=32 -> one wave),
//          REVERSE sweep for L2 reuse of y, x/z evict-first; last block folds
//          the final reduction + output write (threadfence-reduction).

#define FPS_B 32
#define BPB   37            // 37*32 = 1184 blocks = one full wave (148 SM x 8 CTA)

__device__ unsigned long long g_part1[FPS_B * BPB];
__device__ unsigned long long g_part2[FPS_B * BPB];
__device__ unsigned int       g_ticket;

struct F8 { float f[8]; };

// 32-byte read-only load (LDG.E.256). Hi-word extracts are free (register pair).
static __device__ __forceinline__ F8 ldg8(const float* p) {
    unsigned long long a, b, c, d;
    asm("ld.global.nc.v4.b64 {%0,%1,%2,%3}, [%4];"
        : "=l"(a), "=l"(b), "=l"(c), "=l"(d) : "l"(p));
    F8 r;
    r.f[0] = __uint_as_float((unsigned)a);  r.f[1] = __uint_as_float((unsigned)(a >> 32));
    r.f[2] = __uint_as_float((unsigned)b);  r.f[3] = __uint_as_float((unsigned)(b >> 32));
    r.f[4] = __uint_as_float((unsigned)c);  r.f[5] = __uint_as_float((unsigned)(c >> 32));
    r.f[6] = __uint_as_float((unsigned)d);  r.f[7] = __uint_as_float((unsigned)(d >> 32));
    return r;
}

// key = (ordered_float(val) << 32) | ~index : max-key == (max val, min index on tie)
static __device__ __forceinline__ unsigned long long make_key(float v, unsigned idx) {
    unsigned u = __float_as_uint(v);
    u = (u & 0x80000000u) ? ~u : (u | 0x80000000u);
    return ((unsigned long long)u << 32) | (unsigned)(~idx);
}

static __device__ __forceinline__ unsigned long long umax64(unsigned long long a,
                                                            unsigned long long b) {
    return a > b ? a : b;
}

// full block max (result valid in thread 0 of warp 0)
static __device__ __forceinline__ unsigned long long block_reduce_max(unsigned long long v) {
    __shared__ unsigned long long s[8];
    int lane = threadIdx.x & 31;
    int wid  = threadIdx.x >> 5;
    #pragma unroll
    for (int o = 16; o; o >>= 1)
        v = umax64(v, __shfl_down_sync(0xffffffffu, v, o));
    if (lane == 0) s[wid] = v;
    __syncthreads();
    if (wid == 0) {
        v = (lane < (int)(blockDim.x >> 5)) ? s[lane] : 0ull;
        #pragma unroll
        for (int o = 16; o; o >>= 1)
            v = umax64(v, __shfl_down_sync(0xffffffffu, v, o));
    }
    return v;
}

// forward order: keeps FIRST index on tie via >
#define UPD_GT(bv, bi, v, i) do { if ((v) > (bv)) { (bv) = (v); (bi) = (i); } } while (0)
// reverse order: later-seen index is smaller -> prefer on tie via >=
#define UPD_GE(bv, bi, v, i) do { if ((v) >= (bv)) { (bv) = (v); (bi) = (i); } } while (0)

// Pass 1: per-batch argmax over the y-plane (channel 1). Forward sweep so the
// y tail is L2-resident when pass 2's reverse sweep starts. 32B loads, x2 unroll.
__global__ void __launch_bounds__(256, 8)
fps_pass1(const float* __restrict__ xyz, int N) {
    if (blockIdx.x == 0 && blockIdx.y == 0 && threadIdx.x == 0) g_ticket = 0;

    const int b = blockIdx.y;
    const float* yp = xyz + (size_t)b * 3 * N + (size_t)N;
    const int N8 = N >> 3;
    const int S = gridDim.x * blockDim.x;

    float    bv0 = -CUDART_INF_F, bv1 = -CUDART_INF_F;
    unsigned bi0 = 0u, bi1 = 0u;

    int i = blockIdx.x * blockDim.x + threadIdx.x;
    for (; i + S < N8; i += 2 * S) {
        F8 a = ldg8(yp + ((size_t)i << 3));
        F8 c = ldg8(yp + ((size_t)(i + S) << 3));
        unsigned ba = (unsigned)(i << 3);
        unsigned bc = (unsigned)((i + S) << 3);
        #pragma unroll
        for (int e = 0; e < 8; e++) UPD_GT(bv0, bi0, a.f[e], ba + e);
        #pragma unroll
        for (int e = 0; e < 8; e++) UPD_GT(bv1, bi1, c.f[e], bc + e);
    }
    for (; i < N8; i += S) {
        F8 a = ldg8(yp + ((size_t)i << 3));
        unsigned ba = (unsigned)(i << 3);
        #pragma unroll
        for (int e = 0; e < 8; e++) UPD_GT(bv0, bi0, a.f[e], ba + e);
    }
    unsigned long long best = umax64(make_key(bv0, bi0), make_key(bv1, bi1));

    if (blockIdx.x == 0) {   // scalar tail (N % 8)
        float bvt = -CUDART_INF_F; unsigned bit_ = 0u;
        for (int t = (N8 << 3) + threadIdx.x; t < N; t += blockDim.x)
            UPD_GT(bvt, bit_, yp[t], (unsigned)t);
        best = umax64(best, make_key(bvt, bit_));
    }

    best = block_reduce_max(best);
    if (threadIdx.x == 0) g_part1[b * BPB + blockIdx.x] = best;
}

// Pass 2: per-batch argmax of min(1e10, ||p - c0||^2), reverse sweep (single
// accumulator -> regs<=32 -> one full wave). x,z evict-first; y default-cached
// (hot from pass 1). Last block performs the global reduction + output write.
__global__ void __launch_bounds__(256, 8)
fps_pass2(const float* __restrict__ xyz, int N, float* __restrict__ out) {
    const int b = blockIdx.y;

    // reduce pass-1 partials for this batch -> centroid index
    __shared__ unsigned idx0_sh;
    {
        unsigned long long v = (threadIdx.x < BPB) ? g_part1[b * BPB + threadIdx.x] : 0ull;
        v = block_reduce_max(v);
        if (threadIdx.x == 0) idx0_sh = ~(unsigned)v;
        __syncthreads();
    }
    const unsigned idx0 = idx0_sh;

    const float* xp = xyz + (size_t)b * 3 * N;
    const float* yp = xp + (size_t)N;
    const float* zp = xp + (size_t)2 * N;
    const float cx = __ldg(xp + idx0);
    const float cy = __ldg(yp + idx0);
    const float cz = __ldg(zp + idx0);

    const int N4 = N >> 2;
    const float4* x4 = (const float4*)xp;
    const float4* y4 = (const float4*)yp;
    const float4* z4 = (const float4*)zp;
    const int stride = gridDim.x * blockDim.x;

    float    bv = -CUDART_INF_F;
    unsigned bi = 0u;

    // scalar tail first (highest indices), forward order -> '>' keeps first;
    // main loop's GE (strictly smaller indices) correctly overrides ties after.
    if (blockIdx.x == 0) {
        for (int t = (N4 << 2) + threadIdx.x; t < N; t += blockDim.x) {
            float dx = xp[t] - cx, dy = yp[t] - cy, dz = zp[t] - cz;
            float d = fminf(dx * dx + dy * dy + dz * dz, 1e10f);
            UPD_GT(bv, bi, d, (unsigned)t);
        }
    }

    for (int j = blockIdx.x * blockDim.x + threadIdx.x; j < N4; j += stride) {
        int i = N4 - 1 - j;                    // reverse: hot y tail consumed first
        float4 vx = __ldcs(x4 + i);            // streaming, evict-first
        float4 vy = y4[i];                     // hot from pass 1 -> keep cached
        float4 vz = __ldcs(z4 + i);
        unsigned base = (unsigned)(i << 2);
        {
            float dx = vx.x - cx, dy = vy.x - cy, dz = vz.x - cz;
            float d = fminf(dx * dx + dy * dy + dz * dz, 1e10f);
            UPD_GE(bv, bi, d, base + 0);
        }
        {
            float dx = vx.y - cx, dy = vy.y - cy, dz = vz.y - cz;
            float d = fminf(dx * dx + dy * dy + dz * dz, 1e10f);
            UPD_GE(bv, bi, d, base + 1);
        }
        {
            float dx = vx.z - cx, dy = vy.z - cy, dz = vz.z - cz;
            float d = fminf(dx * dx + dy * dy + dz * dz, 1e10f);
            UPD_GE(bv, bi, d, base + 2);
        }
        {
            float dx = vx.w - cx, dy = vy.w - cy, dz = vz.w - cz;
            float d = fminf(dx * dx + dy * dy + dz * dz, 1e10f);
            UPD_GE(bv, bi, d, base + 3);
        }
    }

    unsigned long long best = block_reduce_max(make_key(bv, bi));
    if (threadIdx.x == 0) g_part2[b * BPB + blockIdx.x] = best;

    // ---- folded finalize: last block reduces all partials, writes output ----
    __shared__ bool s_last;
    __threadfence();
    if (threadIdx.x == 0) {
        unsigned t = atomicAdd(&g_ticket, 1u);
        s_last = (t == gridDim.x * gridDim.y - 1);
    }
    __syncthreads();
    if (s_last) {
        int wid  = threadIdx.x >> 5;
        int lane = threadIdx.x & 31;
        for (int bb = wid; bb < FPS_B; bb += (int)(blockDim.x >> 5)) {
            unsigned long long v1 = 0ull, v2 = 0ull;
            for (int k = lane; k < BPB; k += 32) {
                v1 = umax64(v1, g_part1[bb * BPB + k]);
                v2 = umax64(v2, g_part2[bb * BPB + k]);
            }
            #pragma unroll
            for (int o = 16; o; o >>= 1) {
                v1 = umax64(v1, __shfl_down_sync(0xffffffffu, v1, o));
                v2 = umax64(v2, __shfl_down_sync(0xffffffffu, v2, o));
            }
            if (lane == 0) {
                out[2 * bb + 0] = (float)(~(unsigned)v1);   // exact: idx <= 2^24
                out[2 * bb + 1] = (float)(~(unsigned)v2);
            }
        }
    }
}

extern "C" void kernel_launch(void* const* d_in, const int* in_sizes, int n_in,
                              void* d_out, int out_size) {
    const float* xyz = (const float*)d_in[0];
    const int N = in_sizes[0] / (FPS_B * 3);   // [1, 32, 3, N]
    float* out = (float*)d_out;

    const int THREADS = 256;
    fps_pass1<<<dim3(BPB, FPS_B), THREADS>>>(xyz, N);
    fps_pass2<<<dim3(BPB, FPS_B), THREADS>>>(xyz, N, out);
}